// round 8
// baseline (speedup 1.0000x reference)
#include <cuda_runtime.h>
#include <math_constants.h>
#include <cstdint>

// SPP: out = concat(x, pool5(x), pool9(x), pool13(x)) along channels.
// Cascade: pool9 = pool5(pool5(x)), pool13 = pool5(pool9(x)), separable.
//
// R7: one WARP = one CTA = one fully independent pipeline (2 planes).
//  - Compute core (best measured, R3): 16 lanes/plane, width-16 shuffles
//    (OOB self-return = free edge clip), lane owns 2 cols x 32 rows as
//    float2 regs; horizontal 5-max via pair-max factorization (4 SHFL per
//    warp-row covering 2 plane-rows); vertical 5-max via register ring;
//    in-place cascade feeds the next pool.
//  - Drain (R6 win): stage each output section (2 planes = 8 KB) in SMEM,
//    emit ONE cp.async.bulk.global.shared::cta (full-line sequential
//    writes), double-buffered.
//  - R7 change: NO block barriers at all (warp-synchronous; __syncwarp
//    only). 16 KB smem/CTA -> ~14 CTAs/SM (was 3), so ~14 independent bulk
//    queues per SM keep the DRAM write drain saturated.
//
// x: (32, 512, 32, 32) f32 -> out: (32, 2048, 32, 32) f32.

#define NCHAN 512
#define HW 1024
#define PLANES (32 * 512)
#define PLANES_PER_BLK 2
#define SEC_FLOATS (PLANES_PER_BLK * HW)          // 2048 floats
#define SEC_BYTES  (SEC_FLOATS * 4)               // 8192 bytes
#define SMEM_BYTES (2 * SEC_BYTES)                // 16 KB

__device__ __forceinline__ uint32_t smem_u32(const void* p) {
    uint32_t a;
    asm("{ .reg .u64 t; cvta.to.shared.u64 t, %1; cvt.u32.u64 %0, t; }"
        : "=r"(a) : "l"(p));
    return a;
}

__device__ __forceinline__ void bulk_store(const float* dst, uint32_t s_addr) {
    asm volatile("cp.async.bulk.global.shared::cta.bulk_group [%0], [%1], %2;"
                 :: "l"(dst), "r"(s_addr), "n"(SEC_BYTES) : "memory");
    asm volatile("cp.async.bulk.commit_group;" ::: "memory");
}

__global__ __launch_bounds__(32)
void spp_kernel(const float* __restrict__ x, float* __restrict__ out) {
    extern __shared__ float sbuf[];               // [2][SEC_FLOATS]

    const int lane = threadIdx.x;                 // 0..31
    const int sub  = lane >> 4;                   // plane within warp (0/1)
    const int l    = lane & 15;                   // column-pair index

    const int plane0 = blockIdx.x * PLANES_PER_BLK;       // n*512 + c0
    const int plane  = plane0 + sub;
    const int n  = plane0 >> 9;
    const int c0 = plane0 & (NCHAN - 1);

    const float2* __restrict__ xin =
        (const float2*)(x + (size_t)plane * HW) + l;
    const float* __restrict__ ob =
        out + ((size_t)n * (4 * NCHAN) + c0) * HW;        // section stride NCHAN*HW

    // Lane's 2-column strip, all 32 rows, in registers.
    float2 v[32];
    #pragma unroll
    for (int y = 0; y < 32; ++y) v[y] = xin[y * 16];

    // Staging slots for this lane in each buffer.
    float2* stg0 = (float2*)(sbuf)              + sub * (HW / 2) + l;
    float2* stg1 = (float2*)(sbuf + SEC_FLOATS) + sub * (HW / 2) + l;
    const uint32_t s0 = smem_u32(sbuf);
    const uint32_t s1 = smem_u32(sbuf + SEC_FLOATS);

    // ---- section 0: pass-through via bulk store (buffer 0) ----
    #pragma unroll
    for (int y = 0; y < 32; ++y) stg0[y * 16] = v[y];
    __syncwarp();
    if (lane == 0) {
        asm volatile("fence.proxy.async.shared::cta;" ::: "memory");
        bulk_store(ob, s0);
    }

    const unsigned FULL = 0xffffffffu;
    const float NEG = -CUDART_INF_F;

    #pragma unroll
    for (int p = 0; p < 3; ++p) {
        // ---- compute pool p in registers (overlaps prior bulk drains) ----
        float2 r0 = {NEG, NEG}, r1 = {NEG, NEG},
               r2 = {NEG, NEG}, r3 = {NEG, NEG};

        #pragma unroll
        for (int y = 0; y < 34; ++y) {
            float2 h;
            if (y < 32) {
                const float a = v[y].x, b = v[y].y;
                const float pm = fmaxf(a, b);
                const float lp = __shfl_up_sync  (FULL, pm, 1, 16);
                const float lb = __shfl_up_sync  (FULL, b,  1, 16);
                const float ra = __shfl_down_sync(FULL, a,  1, 16);
                const float rp = __shfl_down_sync(FULL, pm, 1, 16);
                h.x = fmaxf(fmaxf(lp, pm), ra);   // cols 2l-2 .. 2l+2
                h.y = fmaxf(fmaxf(lb, pm), rp);   // cols 2l-1 .. 2l+3
            } else {
                h.x = NEG; h.y = NEG;             // bottom padding rows
            }
            if (y >= 2) {
                float2 m;
                m.x = fmaxf(fmaxf(fmaxf(r0.x, r1.x), fmaxf(r2.x, r3.x)), h.x);
                m.y = fmaxf(fmaxf(fmaxf(r0.y, r1.y), fmaxf(r2.y, r3.y)), h.y);
                v[y - 2] = m;                     // in-place: feeds next pool
            }
            r0 = r1; r1 = r2; r2 = r3; r3 = h;
        }

        // ---- stage + bulk store section p+1 (buffers alternate 1,0,1) ----
        const int b = (p + 1) & 1;
        if (p >= 1 && lane == 0) {
            // Buffer b was consumed by the bulk op issued 2 sections ago.
            asm volatile("cp.async.bulk.wait_group.read 1;" ::: "memory");
        }
        __syncwarp();                             // buffer-free known to warp

        float2* stg = b ? stg1 : stg0;
        #pragma unroll
        for (int y = 0; y < 32; ++y) stg[y * 16] = v[y];
        __syncwarp();
        if (lane == 0) {
            asm volatile("fence.proxy.async.shared::cta;" ::: "memory");
            bulk_store(ob + (size_t)(p + 1) * NCHAN * HW, b ? s1 : s0);
        }
    }

    // SMEM must outlive all pending bulk reads.
    if (lane == 0)
        asm volatile("cp.async.bulk.wait_group.read 0;" ::: "memory");
    __syncwarp();
}

extern "C" void kernel_launch(void* const* d_in, const int* in_sizes, int n_in,
                              void* d_out, int out_size) {
    const float* x = (const float*)d_in[0];
    float* out     = (float*)d_out;
    spp_kernel<<<PLANES / PLANES_PER_BLK, 32, SMEM_BYTES>>>(x, out);
}

// round 9
// speedup vs baseline: 1.0146x; 1.0146x over previous
#include <cuda_runtime.h>
#include <math_constants.h>
#include <cstdint>

// SPP: out = concat(x, pool5(x), pool9(x), pool13(x)) along channels.
// Cascade: pool9 = pool5(pool5(x)), pool13 = pool5(pool9(x)), separable.
//
// Structure = R6 (best measured: 50.8us ncu): block = 8 contiguous planes,
// 4 warps; compute core = R3 (warp = 2 planes, width-16 shuffles, pair-max
// horizontal 5-max, register-ring vertical 5-max, in-place cascade).
// Output drains via ONE 32KB cp.async.bulk per section, double-buffered.
//
// R8 change: L2::cache_hint (createpolicy evict_first) on the bulk stores.
// Full-line granularity, so this cannot trigger the R4 sector-RMW disaster;
// goal is prompt, issue-ordered write-back and preserved input residency.
// Also: buffer-recycle wait hoisted BEFORE the compute phase so its latency
// hides under ~10us of register compute.
//
// x: (32, 512, 32, 32) f32 -> out: (32, 2048, 32, 32) f32.

#define NCHAN 512
#define HW 1024
#define PLANES (32 * 512)
#define WARPS_PER_BLK 4
#define PLANES_PER_BLK (WARPS_PER_BLK * 2)
#define SEC_FLOATS (PLANES_PER_BLK * HW)          // 8192 floats
#define SEC_BYTES  (SEC_FLOATS * 4)               // 32768 bytes
#define SMEM_BYTES (2 * SEC_BYTES)                // 64 KB

__device__ __forceinline__ uint32_t smem_u32(const void* p) {
    uint32_t a;
    asm("{ .reg .u64 t; cvta.to.shared.u64 t, %1; cvt.u32.u64 %0, t; }"
        : "=r"(a) : "l"(p));
    return a;
}

__device__ __forceinline__ void bulk_store_ef(const float* dst, uint32_t s) {
    asm volatile(
        "{\n\t"
        ".reg .b64 pol;\n\t"
        "createpolicy.fractional.L2::evict_first.b64 pol, 1.0;\n\t"
        "cp.async.bulk.global.shared::cta.bulk_group.L2::cache_hint "
        "[%0], [%1], %2, pol;\n\t"
        "}"
        :: "l"(dst), "r"(s), "n"(SEC_BYTES) : "memory");
    asm volatile("cp.async.bulk.commit_group;" ::: "memory");
}

__global__ __launch_bounds__(32 * WARPS_PER_BLK)
void spp_kernel(const float* __restrict__ x, float* __restrict__ out) {
    extern __shared__ float sbuf[];               // [2][SEC_FLOATS]

    const int lane = threadIdx.x & 31;
    const int wid  = threadIdx.x >> 5;
    const int sub  = lane >> 4;                   // plane within warp (0/1)
    const int l    = lane & 15;                   // column-pair index

    const int pl_local = wid * 2 + sub;           // 0..7 within block
    const int plane = blockIdx.x * PLANES_PER_BLK + pl_local;   // n*512+c
    const int n  = plane >> 9;
    const int c0 = (blockIdx.x * PLANES_PER_BLK) & (NCHAN - 1);

    const float2* __restrict__ xin =
        (const float2*)(x + (size_t)plane * HW) + l;
    const float* __restrict__ ob =
        out + ((size_t)n * (4 * NCHAN) + c0) * HW;

    // Lane's 2-column strip, all 32 rows, in registers.
    float2 v[32];
    #pragma unroll
    for (int y = 0; y < 32; ++y) v[y] = xin[y * 16];

    float2* stg0 = (float2*)(sbuf)              + pl_local * (HW / 2) + l;
    float2* stg1 = (float2*)(sbuf + SEC_FLOATS) + pl_local * (HW / 2) + l;
    const uint32_t s0 = smem_u32(sbuf);
    const uint32_t s1 = smem_u32(sbuf + SEC_FLOATS);

    // ---- section 0: pass-through via bulk store (buffer 0) ----
    #pragma unroll
    for (int y = 0; y < 32; ++y) stg0[y * 16] = v[y];
    asm volatile("fence.proxy.async.shared::cta;" ::: "memory");
    __syncthreads();
    if (threadIdx.x == 0) bulk_store_ef(ob, s0);

    const unsigned FULL = 0xffffffffu;
    const float NEG = -CUDART_INF_F;

    #pragma unroll
    for (int p = 0; p < 3; ++p) {
        // Recycle check for the buffer we'll stage into AFTER this compute:
        // poll now so the wait hides under the compute phase. Buffer b was
        // consumed by the bulk op issued two sections ago.
        const int b = (p + 1) & 1;
        if (p >= 1 && threadIdx.x == 0)
            asm volatile("cp.async.bulk.wait_group.read 1;" ::: "memory");

        // ---- compute pool p entirely in registers ----
        float2 r0 = {NEG, NEG}, r1 = {NEG, NEG},
               r2 = {NEG, NEG}, r3 = {NEG, NEG};

        #pragma unroll
        for (int y = 0; y < 34; ++y) {
            float2 h;
            if (y < 32) {
                const float a = v[y].x, bb = v[y].y;
                const float pm = fmaxf(a, bb);
                const float lp = __shfl_up_sync  (FULL, pm, 1, 16);
                const float lb = __shfl_up_sync  (FULL, bb, 1, 16);
                const float ra = __shfl_down_sync(FULL, a,  1, 16);
                const float rp = __shfl_down_sync(FULL, pm, 1, 16);
                h.x = fmaxf(fmaxf(lp, pm), ra);   // cols 2l-2 .. 2l+2
                h.y = fmaxf(fmaxf(lb, pm), rp);   // cols 2l-1 .. 2l+3
            } else {
                h.x = NEG; h.y = NEG;             // bottom padding rows
            }
            if (y >= 2) {
                float2 m;
                m.x = fmaxf(fmaxf(fmaxf(r0.x, r1.x), fmaxf(r2.x, r3.x)), h.x);
                m.y = fmaxf(fmaxf(fmaxf(r0.y, r1.y), fmaxf(r2.y, r3.y)), h.y);
                v[y - 2] = m;                     // in-place: feeds next pool
            }
            r0 = r1; r1 = r2; r2 = r3; r3 = h;
        }

        // ---- stage + bulk store section p+1 ----
        __syncthreads();                          // buffer-free known to all

        float2* stg = b ? stg1 : stg0;
        #pragma unroll
        for (int y = 0; y < 32; ++y) stg[y * 16] = v[y];
        asm volatile("fence.proxy.async.shared::cta;" ::: "memory");
        __syncthreads();

        if (threadIdx.x == 0)
            bulk_store_ef(ob + (size_t)(p + 1) * NCHAN * HW, b ? s1 : s0);
    }

    // SMEM must outlive all pending bulk reads.
    if (threadIdx.x == 0)
        asm volatile("cp.async.bulk.wait_group.read 0;" ::: "memory");
    __syncthreads();
}

extern "C" void kernel_launch(void* const* d_in, const int* in_sizes, int n_in,
                              void* d_out, int out_size) {
    const float* x = (const float*)d_in[0];
    float* out     = (float*)d_out;
    cudaFuncSetAttribute(spp_kernel,
                         cudaFuncAttributeMaxDynamicSharedMemorySize, SMEM_BYTES);
    spp_kernel<<<PLANES / PLANES_PER_BLK, 32 * WARPS_PER_BLK, SMEM_BYTES>>>(x, out);
}